// round 6
// baseline (speedup 1.0000x reference)
#include <cuda_runtime.h>
#include <cuda_bf16.h>
#include <cstdint>
#include <cstdio>

#define DEVINL __device__ __forceinline__

namespace s8gemm {

constexpr int MDIM = 4096;
constexpr int KDIM = 4096;
constexpr int NDIM = 8192;

// GEMM tiling
constexpr int BM = 128;
constexpr int BN = 256;
constexpr int KC = 32;                    // k-elems per mainloop step
constexpr int NKT = KDIM / KC;            // 128 steps
constexpr int THREADS = 512;              // 16 warps: 4 (m) x 4 (n)
constexpr int WM = 32;
constexpr int WN = 64;

// Padded smem rows: 40 bf16 = 80 bytes = 5 x 16B (odd 16B stride ->
// 8 ldmatrix row addresses hit 8 distinct 16B banks: conflict-free).
constexpr int RSE = 40;
constexpr int RSB = RSE * 2;              // 80 bytes
constexpr int SA_BYTES = BM * RSB;        // 10240
constexpr int SB_BYTES = BN * RSB;        // 20480
constexpr int STAGE = SA_BYTES + SB_BYTES;// 30720
constexpr int SMEM_ALLOC = 2 * STAGE;     // 61440

constexpr int MT = MDIM / BM;             // 32
constexpr int NT = NDIM / BN;             // 32
constexpr int CTAS = MT * NT;             // 1024

// bf16 scratch: A in-layout, B transposed to [N][K].
__device__ __align__(256) __nv_bfloat16 g_Abf[(size_t)MDIM * KDIM];   // 32 MB
__device__ __align__(256) __nv_bfloat16 g_Btbf[(size_t)NDIM * KDIM];  // 64 MB

// Detected storage dtype of the logically-int8 inputs: 0=int8, 1=int32, 2=fp32
__device__ int g_dtA;
__device__ int g_dtB;

DEVINL uint32_t smem_u32(const void* p) {
    uint32_t a;
    asm("{ .reg .u64 t; cvta.to.shared.u64 t, %1; cvt.u32.u64 %0, t; }" : "=r"(a) : "l"(p));
    return a;
}
DEVINL void cp_async16(uint32_t dst, const void* src) {
    asm volatile("cp.async.cg.shared.global [%0], [%1], 16;" :: "r"(dst), "l"(src) : "memory");
}
DEVINL void cp_commit() { asm volatile("cp.async.commit_group;" ::: "memory"); }
template <int N> DEVINL void cp_wait() {
    asm volatile("cp.async.wait_group %0;" :: "n"(N) : "memory");
}
DEVINL void ldsm_x4(uint32_t (&r)[4], uint32_t addr) {
    asm volatile("ldmatrix.sync.aligned.m8n8.x4.shared.b16 {%0,%1,%2,%3}, [%4];"
                 : "=r"(r[0]), "=r"(r[1]), "=r"(r[2]), "=r"(r[3]) : "r"(addr));
}
DEVINL void mma16816(float (&d)[4], const uint32_t (&a)[4], uint32_t b0, uint32_t b1) {
    asm volatile(
        "mma.sync.aligned.m16n8k16.row.col.f32.bf16.bf16.f32 "
        "{%0,%1,%2,%3}, {%4,%5,%6,%7}, {%8,%9}, {%0,%1,%2,%3};"
        : "+f"(d[0]), "+f"(d[1]), "+f"(d[2]), "+f"(d[3])
        : "r"(a[0]), "r"(a[1]), "r"(a[2]), "r"(a[3]), "r"(b0), "r"(b1));
}

// ---------------------------------------------------------------------------
// Dtype detection: int8 values stored as int32 -> every word in [-128,127].
// Stored as fp32 -> every word, as float, is integral and |v| <= 128.
// Stored as int8 -> packed bytes look like large random 32-bit ints.
// ---------------------------------------------------------------------------
DEVINL int classify(const void* p) {
    const int32_t* w = (const int32_t*)p;
    bool all_i32 = true;
    for (int i = 0; i < 64; ++i) {
        int32_t v = w[i];
        if (v < -128 || v > 127) { all_i32 = false; break; }
    }
    if (all_i32) return 1;
    const float* f = (const float*)p;
    bool all_f32 = true;
    for (int i = 0; i < 64; ++i) {
        float v = f[i];
        if (!(v >= -128.0f && v <= 128.0f) || v != truncf(v)) { all_f32 = false; break; }
    }
    return all_f32 ? 2 : 0;
}

__global__ void detect_kernel(const void* a, const void* b) {
    int da = classify(a);
    int db = classify(b);
    g_dtA = da;
    g_dtB = db;
    printf("DTYPE_PROBE a=%d b=%d a_w0=0x%08x b_w0=0x%08x\n",
           da, db, ((const uint32_t*)a)[0], ((const uint32_t*)b)[0]);
}

// ---------------------------------------------------------------------------
// Pre-pass 1: A (int8 logical, storage per g_dtA) [M][K] -> bf16 [M][K].
// One thread converts 16 consecutive elements.
// ---------------------------------------------------------------------------
__global__ void __launch_bounds__(256) conv_a_kernel(const void* __restrict__ A) {
    const size_t base = ((size_t)blockIdx.x * 256 + threadIdx.x) * 16;
    const int dt = g_dtA;
    __nv_bfloat16 o[16];
    if (dt == 1) {
        const int32_t* p = (const int32_t*)A + base;
        #pragma unroll
        for (int j = 0; j < 16; ++j) o[j] = __float2bfloat16_rn((float)p[j]);
    } else if (dt == 2) {
        const float* p = (const float*)A + base;
        #pragma unroll
        for (int j = 0; j < 16; ++j) o[j] = __float2bfloat16_rn(p[j]);
    } else {
        uint4 v = *reinterpret_cast<const uint4*>((const int8_t*)A + base);
        const int8_t* b = reinterpret_cast<const int8_t*>(&v);
        #pragma unroll
        for (int j = 0; j < 16; ++j) o[j] = __float2bfloat16_rn((float)(int)b[j]);
    }
    *reinterpret_cast<uint4*>(&g_Abf[base])     = *reinterpret_cast<uint4*>(&o[0]);
    *reinterpret_cast<uint4*>(&g_Abf[base + 8]) = *reinterpret_cast<uint4*>(&o[8]);
}

// ---------------------------------------------------------------------------
// Pre-pass 2: B (int8 logical, storage per g_dtB) [K][N] -> Bt bf16 [N][K].
// 64x64 smem-tiled transpose; grid = (N/64, K/64), 256 threads.
// ---------------------------------------------------------------------------
__global__ void __launch_bounds__(256) conv_b_kernel(const void* __restrict__ B) {
    __shared__ __nv_bfloat16 t[64][65];
    const int n0 = blockIdx.x * 64, k0 = blockIdx.y * 64;
    const int r  = threadIdx.x >> 2;          // 0..63
    const int c  = (threadIdx.x & 3) * 16;    // 0,16,32,48
    const int dt = g_dtB;

    const size_t src_off = (size_t)(k0 + r) * NDIM + n0 + c;
    if (dt == 1) {
        const int32_t* p = (const int32_t*)B + src_off;
        #pragma unroll
        for (int j = 0; j < 16; ++j) t[r][c + j] = __float2bfloat16_rn((float)p[j]);
    } else if (dt == 2) {
        const float* p = (const float*)B + src_off;
        #pragma unroll
        for (int j = 0; j < 16; ++j) t[r][c + j] = __float2bfloat16_rn(p[j]);
    } else {
        uint4 v = *reinterpret_cast<const uint4*>((const int8_t*)B + src_off);
        const int8_t* b = reinterpret_cast<const int8_t*>(&v);
        #pragma unroll
        for (int j = 0; j < 16; ++j) t[r][c + j] = __float2bfloat16_rn((float)(int)b[j]);
    }
    __syncthreads();

    __nv_bfloat16 o[16];
    #pragma unroll
    for (int j = 0; j < 16; ++j) o[j] = t[c + j][r];           // Bt[n0+r][k0+c+j]
    __nv_bfloat16* dst = &g_Btbf[(size_t)(n0 + r) * KDIM + k0 + c];
    *reinterpret_cast<uint4*>(dst)     = *reinterpret_cast<uint4*>(&o[0]);
    *reinterpret_cast<uint4*>(dst + 8) = *reinterpret_cast<uint4*>(&o[8]);
}

// ---------------------------------------------------------------------------
// Main GEMM: bf16 mma.sync (m16n8k16), double-buffered cp.async.
// (Unchanged from R5 — audited against PTX fragment layouts.)
// ---------------------------------------------------------------------------
__global__ void __launch_bounds__(THREADS, 1)
bf16_mma_gemm_kernel(const float* __restrict__ scale, float* __restrict__ out)
{
    extern __shared__ char smem[];
    const uint32_t sb = smem_u32(smem);

    const int tid  = threadIdx.x;
    const int wid  = tid >> 5;
    const int lane = tid & 31;

    const int mt = blockIdx.x & 31;   // m-fastest raster: A panel L2-warm
    const int nt = blockIdx.x >> 5;
    const int m0 = mt * BM;
    const int n0 = nt * BN;

    const int wm = (wid >> 2) * WM;
    const int wn = (wid & 3) * WN;

    const __nv_bfloat16* gA = g_Abf  + (size_t)m0 * KDIM;
    const __nv_bfloat16* gB = g_Btbf + (size_t)n0 * KDIM;

    auto fill = [&](int buf, int kt) {
        const uint32_t base = sb + buf * STAGE;
        #pragma unroll
        for (int j = 0; j < 3; ++j) {
            const int q = tid + j * THREADS;
            if (q < 512) {
                const int r = q >> 2, c = q & 3;
                cp_async16(base + r * RSB + c * 16,
                           gA + (size_t)r * KDIM + kt * KC + c * 8);
            } else {
                const int qb = q - 512;
                const int r = qb >> 2, c = qb & 3;
                cp_async16(base + SA_BYTES + r * RSB + c * 16,
                           gB + (size_t)r * KDIM + kt * KC + c * 8);
            }
        }
        cp_commit();
    };

    float acc[2][8][4];
    #pragma unroll
    for (int mi = 0; mi < 2; ++mi)
        #pragma unroll
        for (int nf = 0; nf < 8; ++nf)
            #pragma unroll
            for (int k = 0; k < 4; ++k) acc[mi][nf][k] = 0.0f;

    const int lr  = lane & 15;
    const int lh  = (lane >> 4) * 16;

    fill(0, 0);

    for (int kt = 0; kt < NKT; ++kt) {
        if (kt + 1 < NKT) fill((kt + 1) & 1, kt + 1);

        if (kt + 1 < NKT) cp_wait<1>(); else cp_wait<0>();
        __syncthreads();

        const uint32_t aB = sb + (kt & 1) * STAGE;
        const uint32_t bB = aB + SA_BYTES;

        #pragma unroll
        for (int s = 0; s < 2; ++s) {
            const int kb = s * 32;
            uint32_t av[2][4];
            #pragma unroll
            for (int mi = 0; mi < 2; ++mi)
                ldsm_x4(av[mi], aB + (wm + mi * 16 + lr) * RSB + kb + lh);
            uint32_t bv[4][4];
            #pragma unroll
            for (int nb = 0; nb < 4; ++nb)
                ldsm_x4(bv[nb], bB + (wn + nb * 16 + lr) * RSB + kb + lh);
            #pragma unroll
            for (int mi = 0; mi < 2; ++mi) {
                #pragma unroll
                for (int nb = 0; nb < 4; ++nb) {
                    mma16816(acc[mi][nb * 2 + 0], av[mi], bv[nb][0], bv[nb][2]);
                    mma16816(acc[mi][nb * 2 + 1], av[mi], bv[nb][1], bv[nb][3]);
                }
            }
        }
        __syncthreads();
    }

    const int g  = lane >> 2;
    const int t4 = lane & 3;
    #pragma unroll
    for (int mi = 0; mi < 2; ++mi) {
        const int mrow = m0 + wm + mi * 16 + g;
        #pragma unroll
        for (int nf = 0; nf < 8; ++nf) {
            const int ncol = n0 + wn + nf * 8 + t4 * 2;
            const float s0 = __ldg(&scale[ncol]);
            const float s1 = __ldg(&scale[ncol + 1]);
            float2 v0 = make_float2(acc[mi][nf][0] * s0, acc[mi][nf][1] * s1);
            float2 v1 = make_float2(acc[mi][nf][2] * s0, acc[mi][nf][3] * s1);
            *reinterpret_cast<float2*>(out + (size_t)mrow * NDIM + ncol) = v0;
            *reinterpret_cast<float2*>(out + (size_t)(mrow + 8) * NDIM + ncol) = v1;
        }
    }
}

} // namespace s8gemm

extern "C" void kernel_launch(void* const* d_in, const int* in_sizes, int n_in,
                              void* d_out, int out_size)
{
    using namespace s8gemm;

    // Size-based routing: immune to input ordering.
    const void* pa = nullptr;   // 4096*4096  = 16777216 elems
    const void* pb = nullptr;   // 4096*8192  = 33554432 elems
    const float* ps = nullptr;  // 8192 elems
    for (int i = 0; i < n_in; ++i) {
        if (in_sizes[i] == MDIM * KDIM)            pa = d_in[i];
        else if (in_sizes[i] == KDIM * NDIM)       pb = d_in[i];
        else if (in_sizes[i] == NDIM)              ps = (const float*)d_in[i];
    }
    if (!pa) pa = d_in[0];
    if (!pb) pb = d_in[1];
    if (!ps) ps = (const float*)d_in[2];
    float* out = (float*)d_out;
    (void)out_size;

    fprintf(stderr, "KL_PROBE n_in=%d sizes=[%d,%d,%d]\n",
            n_in, in_sizes[0], n_in > 1 ? in_sizes[1] : -1, n_in > 2 ? in_sizes[2] : -1);

    detect_kernel<<<1, 1>>>(pa, pb);

    {
        const size_t a_chunks = (size_t)MDIM * KDIM / 16;
        conv_a_kernel<<<(unsigned)(a_chunks / 256), 256>>>(pa);
        dim3 gb(NDIM / 64, KDIM / 64);
        conv_b_kernel<<<gb, 256>>>(pb);
    }

    cudaFuncSetAttribute(bf16_mma_gemm_kernel,
                         cudaFuncAttributeMaxDynamicSharedMemorySize, SMEM_ALLOC);
    bf16_mma_gemm_kernel<<<CTAS, THREADS, SMEM_ALLOC>>>(ps, out);
}

// round 7
// speedup vs baseline: 3.2602x; 3.2602x over previous
#include <cuda_runtime.h>
#include <cuda_bf16.h>
#include <cstdint>

#define DEVINL __device__ __forceinline__

#if defined(__CUDA_ARCH__) && \
    (defined(__CUDA_ARCH_FEAT_SM103_ALL) || defined(__CUDA_ARCH_FEAT_SM100_ALL) || \
     defined(__CUDA_ARCH_FEAT_SM101_ALL) || defined(__CUDA_ARCH_SPECIFIC__) || \
     defined(__CUDA_ARCH_FAMILY_SPECIFIC__))
#define HAS_TCGEN05 1
#else
#define HAS_TCGEN05 0
#endif

namespace s8gemm {

constexpr int MDIM = 4096;
constexpr int KDIM = 4096;
constexpr int NDIM = 8192;

// ---- tcgen05 tiling ----
constexpr int BM = 128;
constexpr int BN = 256;          // two N=128 MMA halves
constexpr int BKE = 64;          // K elems per tile (bf16) = 128 bytes
constexpr int NSTAGE = 3;
constexpr int NKT = KDIM / BKE;  // 64 k-tiles

constexpr int A_TILE = BM * 128;             // 16384 B
constexpr int B_TILE = BN * 128;             // 32768 B
constexpr int STAGE_BYTES = A_TILE + B_TILE; // 49152
constexpr int OFF_BAR   = NSTAGE * STAGE_BYTES;   // 147456
constexpr int OFF_SCALE = OFF_BAR + 64;
constexpr int SMEM_ALLOC = OFF_SCALE + BN * 4 + 1024;   // ~149.6 KB

constexpr int TMEM_COLS = 256;
constexpr int MT = MDIM / BM;    // 32
constexpr int NTL = NDIM / BN;   // 32
constexpr int CTAS = MT * NTL;   // 1024
constexpr int THREADS = 512;

// kind::f16 idesc: F32 acc (1<<4), A=BF16 (1<<7), B=BF16 (1<<10),
// N/8<<17, M/16<<24. Both operands K-major -> D = A @ Bt^T = A @ B.
constexpr uint32_t IDESC =
      (1u << 4) | (1u << 7) | (1u << 10)
    | ((128u / 8u) << 17) | ((128u / 16u) << 24);

// K-major SW128 SMEM descriptor (Blackwell version=1): LBO=1, SBO=64.
constexpr uint64_t DESC_BASE_K =
      (uint64_t(2) << 61) | (uint64_t(1) << 46) | (uint64_t(64) << 32) | (uint64_t(1) << 16);

// Scratch. tcgen05 build: pre-swizzled SMEM tile images
//   A block (mt*NKT+kt) = 16KB, B block (nt*NKT+kt) = 32KB.
// Fallback build: same arrays hold linear bf16 A[M][K] / Bt[N][K].
__device__ __align__(1024) uint8_t g_Aimg[(size_t)MT * NKT * A_TILE];    // 32 MB
__device__ __align__(1024) uint8_t g_Bimg[(size_t)NTL * NKT * B_TILE];   // 64 MB

// Detected storage dtype of the logically-int8 inputs: 0=int8, 1=int32, 2=fp32
__device__ int g_dtA;
__device__ int g_dtB;

DEVINL uint32_t smem_u32(const void* p) {
    uint32_t a;
    asm("{ .reg .u64 t; cvta.to.shared.u64 t, %1; cvt.u32.u64 %0, t; }" : "=r"(a) : "l"(p));
    return a;
}
DEVINL uint32_t sw128(uint32_t off) { return off ^ ((off >> 3) & 0x70u); }

// ---------------------------------------------------------------------------
// Dtype detection
// ---------------------------------------------------------------------------
DEVINL int classify(const void* p) {
    const int32_t* w = (const int32_t*)p;
    bool all_i32 = true;
    for (int i = 0; i < 64; ++i) {
        int32_t v = w[i];
        if (v < -128 || v > 127) { all_i32 = false; break; }
    }
    if (all_i32) return 1;
    const float* f = (const float*)p;
    bool all_f32 = true;
    for (int i = 0; i < 64; ++i) {
        float v = f[i];
        if (!(v >= -128.0f && v <= 128.0f) || v != truncf(v)) { all_f32 = false; break; }
    }
    return all_f32 ? 2 : 0;
}
__global__ void detect_kernel(const void* a, const void* b) {
    g_dtA = classify(a);
    g_dtB = classify(b);
}

// ---------------------------------------------------------------------------
// Pre-pass 1: A -> bf16. tcgen05 build: swizzled tile image. Else: linear.
// One thread converts 16 consecutive K-elems of one row.
// ---------------------------------------------------------------------------
__global__ void __launch_bounds__(256) conv_a_kernel(const void* __restrict__ A) {
    const size_t base = ((size_t)blockIdx.x * 256 + threadIdx.x) * 16;
    const int dt = g_dtA;
    __nv_bfloat16 o[16];
    if (dt == 1) {
        const int32_t* p = (const int32_t*)A + base;
        #pragma unroll
        for (int j = 0; j < 16; ++j) o[j] = __float2bfloat16_rn((float)p[j]);
    } else if (dt == 2) {
        const float* p = (const float*)A + base;
        #pragma unroll
        for (int j = 0; j < 16; ++j) o[j] = __float2bfloat16_rn(p[j]);
    } else {
        uint4 v = *reinterpret_cast<const uint4*>((const int8_t*)A + base);
        const int8_t* b = reinterpret_cast<const int8_t*>(&v);
        #pragma unroll
        for (int j = 0; j < 16; ++j) o[j] = __float2bfloat16_rn((float)(int)b[j]);
    }
#if HAS_TCGEN05
    const uint32_t m  = (uint32_t)(base >> 12);          // base / KDIM
    const uint32_t k  = (uint32_t)(base & 4095);
    const uint32_t mt = m >> 7, r = m & 127;
    const uint32_t kt = k >> 6, kl = k & 63;             // kl in {0,16,32,48}
    uint8_t* blk = g_Aimg + (size_t)(mt * NKT + kt) * A_TILE;
    *reinterpret_cast<uint4*>(blk + sw128(r * 128 + kl * 2))      = *reinterpret_cast<uint4*>(&o[0]);
    *reinterpret_cast<uint4*>(blk + sw128(r * 128 + kl * 2 + 16)) = *reinterpret_cast<uint4*>(&o[8]);
#else
    __nv_bfloat16* dst = reinterpret_cast<__nv_bfloat16*>(g_Aimg) + base;
    *reinterpret_cast<uint4*>(dst)     = *reinterpret_cast<uint4*>(&o[0]);
    *reinterpret_cast<uint4*>(dst + 8) = *reinterpret_cast<uint4*>(&o[8]);
#endif
}

// ---------------------------------------------------------------------------
// Pre-pass 2: B [K][N] -> Bt bf16 [N][K] (64x64 smem transpose).
// tcgen05 build: swizzled tile image. Else: linear Bt.
// grid = (N/64, K/64), 256 threads.
// ---------------------------------------------------------------------------
__global__ void __launch_bounds__(256) conv_b_kernel(const void* __restrict__ B) {
    __shared__ __nv_bfloat16 t[64][65];
    const int n0 = blockIdx.x * 64, k0 = blockIdx.y * 64;
    const int r  = threadIdx.x >> 2;
    const int c  = (threadIdx.x & 3) * 16;
    const int dt = g_dtB;

    const size_t src_off = (size_t)(k0 + r) * NDIM + n0 + c;
    if (dt == 1) {
        const int32_t* p = (const int32_t*)B + src_off;
        #pragma unroll
        for (int j = 0; j < 16; ++j) t[r][c + j] = __float2bfloat16_rn((float)p[j]);
    } else if (dt == 2) {
        const float* p = (const float*)B + src_off;
        #pragma unroll
        for (int j = 0; j < 16; ++j) t[r][c + j] = __float2bfloat16_rn(p[j]);
    } else {
        uint4 v = *reinterpret_cast<const uint4*>((const int8_t*)B + src_off);
        const int8_t* b = reinterpret_cast<const int8_t*>(&v);
        #pragma unroll
        for (int j = 0; j < 16; ++j) t[r][c + j] = __float2bfloat16_rn((float)(int)b[j]);
    }
    __syncthreads();

    __nv_bfloat16 o[16];
    #pragma unroll
    for (int j = 0; j < 16; ++j) o[j] = t[c + j][r];     // Bt[n0+r][k0+c+j]

#if HAS_TCGEN05
    const uint32_t ng = n0 + r;
    const uint32_t nt = ng >> 8, nl = ng & 255;
    const uint32_t kt = (uint32_t)k0 >> 6;               // c+j < 64: single k-tile
    uint8_t* blk = g_Bimg + (size_t)(nt * NKT + kt) * B_TILE;
    *reinterpret_cast<uint4*>(blk + sw128(nl * 128 + c * 2))      = *reinterpret_cast<uint4*>(&o[0]);
    *reinterpret_cast<uint4*>(blk + sw128(nl * 128 + c * 2 + 16)) = *reinterpret_cast<uint4*>(&o[8]);
#else
    __nv_bfloat16* dst = reinterpret_cast<__nv_bfloat16*>(g_Bimg) +
                         (size_t)(n0 + r) * KDIM + k0 + c;
    *reinterpret_cast<uint4*>(dst)     = *reinterpret_cast<uint4*>(&o[0]);
    *reinterpret_cast<uint4*>(dst + 8) = *reinterpret_cast<uint4*>(&o[8]);
#endif
}

#if HAS_TCGEN05
DEVINL void mbar_init(uint32_t bar, uint32_t cnt) {
    asm volatile("mbarrier.init.shared.b64 [%0], %1;" :: "r"(bar), "r"(cnt) : "memory");
}
DEVINL void mbar_wait(uint32_t bar, uint32_t parity) {
    asm volatile(
        "{\n\t"
        ".reg .pred P;\n\t"
        "WAIT_%=:\n\t"
        "mbarrier.try_wait.parity.acquire.cta.shared::cta.b64 P, [%0], %1, 0x989680;\n\t"
        "@P bra.uni DONE_%=;\n\t"
        "bra.uni WAIT_%=;\n\t"
        "DONE_%=:\n\t"
        "}" :: "r"(bar), "r"(parity) : "memory");
}
DEVINL void mbar_expect_tx(uint32_t bar, uint32_t bytes) {
    asm volatile("mbarrier.arrive.expect_tx.shared.b64 _, [%0], %1;"
                 :: "r"(bar), "r"(bytes) : "memory");
}
DEVINL void bulk_g2s(uint32_t dst, const void* src, uint32_t bytes, uint32_t bar) {
    asm volatile(
        "cp.async.bulk.shared::cluster.global.mbarrier::complete_tx::bytes [%0], [%1], %2, [%3];"
        :: "r"(dst), "l"(src), "r"(bytes), "r"(bar) : "memory");
}
DEVINL void mma_bf16(uint32_t d, uint64_t ad, uint64_t bd, uint32_t idesc, uint32_t acc) {
    asm volatile(
        "{\n\t.reg .pred p;\n\t"
        "setp.ne.u32 p, %5, 0;\n\t"
        "tcgen05.mma.cta_group::1.kind::f16 [%0], %1, %2, %3, {%4, %4, %4, %4}, p;\n\t}"
        :: "r"(d), "l"(ad), "l"(bd), "r"(idesc), "r"(0u), "r"(acc) : "memory");
}
DEVINL void tc_commit(uint32_t bar) {
    asm volatile("tcgen05.commit.cta_group::1.mbarrier::arrive::one.shared::cluster.b64 [%0];"
                 :: "r"(bar) : "memory");
}
DEVINL void tc_fence_after() { asm volatile("tcgen05.fence::after_thread_sync;" ::: "memory"); }
DEVINL void tc_wait_ld() { asm volatile("tcgen05.wait::ld.sync.aligned;" ::: "memory"); }

#define TC_LD_X32(r, addr)                                                     \
    asm volatile(                                                              \
        "tcgen05.ld.sync.aligned.32x32b.x32.b32 "                              \
        "{%0, %1, %2, %3, %4, %5, %6, %7, "                                    \
        " %8, %9, %10, %11, %12, %13, %14, %15, "                              \
        " %16, %17, %18, %19, %20, %21, %22, %23, "                            \
        " %24, %25, %26, %27, %28, %29, %30, %31}, [%32];"                     \
        : "=r"((r)[0]),  "=r"((r)[1]),  "=r"((r)[2]),  "=r"((r)[3]),           \
          "=r"((r)[4]),  "=r"((r)[5]),  "=r"((r)[6]),  "=r"((r)[7]),           \
          "=r"((r)[8]),  "=r"((r)[9]),  "=r"((r)[10]), "=r"((r)[11]),          \
          "=r"((r)[12]), "=r"((r)[13]), "=r"((r)[14]), "=r"((r)[15]),          \
          "=r"((r)[16]), "=r"((r)[17]), "=r"((r)[18]), "=r"((r)[19]),          \
          "=r"((r)[20]), "=r"((r)[21]), "=r"((r)[22]), "=r"((r)[23]),          \
          "=r"((r)[24]), "=r"((r)[25]), "=r"((r)[26]), "=r"((r)[27]),          \
          "=r"((r)[28]), "=r"((r)[29]), "=r"((r)[30]), "=r"((r)[31])           \
        : "r"(addr))
#else
// Fallback engine helpers (mma.sync), compute_103 phase only.
DEVINL void cp_async16(uint32_t dst, const void* src) {
    asm volatile("cp.async.cg.shared.global [%0], [%1], 16;" :: "r"(dst), "l"(src) : "memory");
}
DEVINL void cp_commit() { asm volatile("cp.async.commit_group;" ::: "memory"); }
template <int N> DEVINL void cp_wait() {
    asm volatile("cp.async.wait_group %0;" :: "n"(N) : "memory");
}
DEVINL void ldsm_x4(uint32_t (&r)[4], uint32_t addr) {
    asm volatile("ldmatrix.sync.aligned.m8n8.x4.shared.b16 {%0,%1,%2,%3}, [%4];"
                 : "=r"(r[0]), "=r"(r[1]), "=r"(r[2]), "=r"(r[3]) : "r"(addr));
}
DEVINL void mma16816(float (&d)[4], const uint32_t (&a)[4], uint32_t b0, uint32_t b1) {
    asm volatile(
        "mma.sync.aligned.m16n8k16.row.col.f32.bf16.bf16.f32 "
        "{%0,%1,%2,%3}, {%4,%5,%6,%7}, {%8,%9}, {%0,%1,%2,%3};"
        : "+f"(d[0]), "+f"(d[1]), "+f"(d[2]), "+f"(d[3])
        : "r"(a[0]), "r"(a[1]), "r"(a[2]), "r"(a[3]), "r"(b0), "r"(b1));
}
#endif

__global__ void __launch_bounds__(THREADS, 1)
gemm_kernel(const float* __restrict__ scale, float* __restrict__ out)
{
    extern __shared__ char smem_raw[];

#if HAS_TCGEN05
    // =========================================================================
    // tcgen05 pipeline: 2 bulk copies/stage, 3 stages, 16-warp epilogue.
    // =========================================================================
    const uint32_t sb_raw = smem_u32(smem_raw);
    const uint32_t sb = (sb_raw + 1023u) & ~1023u;
    char* smem = smem_raw + (sb - sb_raw);

    const int tid = threadIdx.x;
    const int wid = tid >> 5;

    const int mt = blockIdx.x & 31;   // m-fastest raster: A panel L2-warm
    const int nt = blockIdx.x >> 5;
    const int m0 = mt * BM;
    const int n0 = nt * BN;

    const uint32_t bar_full0  = sb + OFF_BAR;
    const uint32_t bar_empty0 = sb + OFF_BAR + 24;
    const uint32_t bar_done   = sb + OFF_BAR + 48;
    const uint32_t tmem_ptr   = sb + OFF_BAR + 56;
    float* s_scale = reinterpret_cast<float*>(smem + OFF_SCALE);

    if (tid == 0) {
        #pragma unroll
        for (int s = 0; s < NSTAGE; ++s) {
            mbar_init(bar_full0 + s * 8, 1);
            mbar_init(bar_empty0 + s * 8, 1);
        }
        mbar_init(bar_done, 1);
    }
    if (wid == 0) {
        asm volatile("tcgen05.alloc.cta_group::1.sync.aligned.shared::cta.b32 [%0], %1;"
                     :: "r"(tmem_ptr), "r"(TMEM_COLS) : "memory");
    }
    if (tid < 256) s_scale[tid] = scale[n0 + tid];
    __syncthreads();

    uint32_t tmem;
    asm volatile("ld.shared.b32 %0, [%1];" : "=r"(tmem) : "r"(tmem_ptr));

    if (tid == 0) {
        // -------- consumer: wait full, 8 MMAs, commit empty --------
        int s = 0, ph = 0;
        for (int kt = 0; kt < NKT; ++kt) {
            mbar_wait(bar_full0 + s * 8, ph);
            const uint32_t stg = sb + (uint32_t)s * STAGE_BYTES;
            const uint64_t adesc = DESC_BASE_K | ((stg >> 4) & 0x3FFFu);
            #pragma unroll
            for (int h = 0; h < 2; ++h) {
                const uint64_t bdesc = DESC_BASE_K |
                    (((stg + A_TILE + (uint32_t)h * 16384u) >> 4) & 0x3FFFu);
                #pragma unroll
                for (int q = 0; q < 4; ++q) {
                    mma_bf16(tmem + h * 128,
                             adesc + (uint64_t)(q * 2),
                             bdesc + (uint64_t)(q * 2),
                             IDESC,
                             (kt > 0 || q > 0) ? 1u : 0u);
                }
            }
            tc_commit(bar_empty0 + s * 8);
            if (++s == NSTAGE) { s = 0; ph ^= 1; }
        }
        tc_commit(bar_done);
    } else if (tid == 32) {
        // -------- producer: wait empty, expect_tx, 2 bulk copies --------
        const uint8_t* gA = g_Aimg + (size_t)(mt * NKT) * A_TILE;
        const uint8_t* gB = g_Bimg + (size_t)(nt * NKT) * B_TILE;
        int s = 0, ph = 1;   // fresh barrier: parity-1 wait passes immediately
        for (int kt = 0; kt < NKT; ++kt) {
            mbar_wait(bar_empty0 + s * 8, ph);
            const uint32_t stg  = sb + (uint32_t)s * STAGE_BYTES;
            const uint32_t barf = bar_full0 + s * 8;
            mbar_expect_tx(barf, (uint32_t)STAGE_BYTES);
            bulk_g2s(stg,          gA + (size_t)kt * A_TILE, (uint32_t)A_TILE, barf);
            bulk_g2s(stg + A_TILE, gB + (size_t)kt * B_TILE, (uint32_t)B_TILE, barf);
            if (++s == NSTAGE) { s = 0; ph ^= 1; }
        }
    }

    // -------- epilogue: 16 warps; wg g owns 64 cols, subpartition wid%4 ------
    mbar_wait(bar_done, 0);
    tc_fence_after();

    const int lane = tid & 31;
    const int g    = wid >> 2;          // warpgroup 0..3 -> col block g*64
    const int sp   = wid & 3;           // TMEM subpartition (rows sp*32..)
    const int mrow = m0 + sp * 32 + lane;
    float* orow = out + (size_t)mrow * NDIM + n0 + g * 64;

    #pragma unroll
    for (int half = 0; half < 2; ++half) {
        uint32_t r[32];
        TC_LD_X32(r, tmem + g * 64 + half * 32);
        tc_wait_ld();
        const float* sc = s_scale + g * 64 + half * 32;
        #pragma unroll
        for (int i = 0; i < 32; i += 4) {
            float4 v;
            v.x = __uint_as_float(r[i + 0]) * sc[i + 0];
            v.y = __uint_as_float(r[i + 1]) * sc[i + 1];
            v.z = __uint_as_float(r[i + 2]) * sc[i + 2];
            v.w = __uint_as_float(r[i + 3]) * sc[i + 3];
            *reinterpret_cast<float4*>(orow + half * 32 + i) = v;
        }
    }

    __syncthreads();
    if (wid == 0) {
        asm volatile("tcgen05.dealloc.cta_group::1.sync.aligned.b32 %0, %1;"
                     :: "r"(tmem), "r"(TMEM_COLS));
    }

#else
    // =========================================================================
    // Fallback (compute_103 phase): proven mma.sync engine on linear scratch.
    // =========================================================================
    constexpr int KC = 32;
    constexpr int NKT2 = KDIM / KC;
    constexpr int RSB = 80;                    // 40 bf16 padded rows
    constexpr int SA_BYTES = BM * RSB;         // 10240
    constexpr int SB_BYTES = BN * RSB;         // 20480
    constexpr int STAGE = SA_BYTES + SB_BYTES; // 30720

    const uint32_t sb = smem_u32(smem_raw);
    const int tid  = threadIdx.x;
    const int wid  = tid >> 5;
    const int lane = tid & 31;

    const int mt = blockIdx.x & 31;
    const int nt = blockIdx.x >> 5;
    const int m0 = mt * BM;
    const int n0 = nt * BN;

    const int wm = (wid >> 2) * 32;
    const int wn = (wid & 3) * 64;

    const __nv_bfloat16* gA = reinterpret_cast<const __nv_bfloat16*>(g_Aimg) + (size_t)m0 * KDIM;
    const __nv_bfloat16* gB = reinterpret_cast<const __nv_bfloat16*>(g_Bimg) + (size_t)n0 * KDIM;

    auto fill = [&](int buf, int kt) {
        const uint32_t base = sb + buf * STAGE;
        #pragma unroll
        for (int j = 0; j < 3; ++j) {
            const int q = tid + j * THREADS;
            if (q < 512) {
                const int r = q >> 2, c = q & 3;
                cp_async16(base + r * RSB + c * 16, gA + (size_t)r * KDIM + kt * KC + c * 8);
            } else {
                const int qb = q - 512;
                const int r = qb >> 2, c = qb & 3;
                cp_async16(base + SA_BYTES + r * RSB + c * 16,
                           gB + (size_t)r * KDIM + kt * KC + c * 8);
            }
        }
        cp_commit();
    };

    float acc[2][8][4];
    #pragma unroll
    for (int mi = 0; mi < 2; ++mi)
        #pragma unroll
        for (int nf = 0; nf < 8; ++nf)
            #pragma unroll
            for (int k = 0; k < 4; ++k) acc[mi][nf][k] = 0.0f;

    const int lr = lane & 15;
    const int lh = (lane >> 4) * 16;

    fill(0, 0);

    for (int kt = 0; kt < NKT2; ++kt) {
        if (kt + 1 < NKT2) fill((kt + 1) & 1, kt + 1);
        if (kt + 1 < NKT2) cp_wait<1>(); else cp_wait<0>();
        __syncthreads();

        const uint32_t aB = sb + (kt & 1) * STAGE;
        const uint32_t bB = aB + SA_BYTES;

        #pragma unroll
        for (int s = 0; s < 2; ++s) {
            const int kb = s * 32;
            uint32_t av[2][4];
            #pragma unroll
            for (int mi = 0; mi < 2; ++mi)
                ldsm_x4(av[mi], aB + (wm + mi * 16 + lr) * RSB + kb + lh);
            uint32_t bv[4][4];
            #pragma unroll
            for (int nb = 0; nb < 4; ++nb)
                ldsm_x4(bv[nb], bB + (wn + nb * 16 + lr) * RSB + kb + lh);
            #pragma unroll
            for (int mi = 0; mi < 2; ++mi) {
                #pragma unroll
                for (int nb = 0; nb < 4; ++nb) {
                    mma16816(acc[mi][nb * 2 + 0], av[mi], bv[nb][0], bv[nb][2]);
                    mma16816(acc[mi][nb * 2 + 1], av[mi], bv[nb][1], bv[nb][3]);
                }
            }
        }
        __syncthreads();
    }

    const int g  = lane >> 2;
    const int t4 = lane & 3;
    #pragma unroll
    for (int mi = 0; mi < 2; ++mi) {
        const int mrow = m0 + wm + mi * 16 + g;
        #pragma unroll
        for (int nf = 0; nf < 8; ++nf) {
            const int ncol = n0 + wn + nf * 8 + t4 * 2;
            const float s0 = __ldg(&scale[ncol]);
            const float s1 = __ldg(&scale[ncol + 1]);
            float2 v0 = make_float2(acc[mi][nf][0] * s0, acc[mi][nf][1] * s1);
            float2 v1 = make_float2(acc[mi][nf][2] * s0, acc[mi][nf][3] * s1);
            *reinterpret_cast<float2*>(out + (size_t)mrow * NDIM + ncol) = v0;
            *reinterpret_cast<float2*>(out + (size_t)(mrow + 8) * NDIM + ncol) = v1;
        }
    }
#endif
}

} // namespace s8gemm

extern "C" void kernel_launch(void* const* d_in, const int* in_sizes, int n_in,
                              void* d_out, int out_size)
{
    using namespace s8gemm;

    const void* pa = nullptr;
    const void* pb = nullptr;
    const float* ps = nullptr;
    for (int i = 0; i < n_in; ++i) {
        if (in_sizes[i] == MDIM * KDIM)      pa = d_in[i];
        else if (in_sizes[i] == KDIM * NDIM) pb = d_in[i];
        else if (in_sizes[i] == NDIM)        ps = (const float*)d_in[i];
    }
    if (!pa) pa = d_in[0];
    if (!pb) pb = d_in[1];
    if (!ps) ps = (const float*)d_in[2];
    float* out = (float*)d_out;
    (void)out_size;

    detect_kernel<<<1, 1>>>(pa, pb);
    {
        const size_t a_chunks = (size_t)MDIM * KDIM / 16;
        conv_a_kernel<<<(unsigned)(a_chunks / 256), 256>>>(pa);
        dim3 gb(NDIM / 64, KDIM / 64);
        conv_b_kernel<<<gb, 256>>>(pb);
    }

    cudaFuncSetAttribute(gemm_kernel,
                         cudaFuncAttributeMaxDynamicSharedMemorySize, SMEM_ALLOC);
    gemm_kernel<<<CTAS, THREADS, SMEM_ALLOC>>>(ps, out);
}